// round 1
// baseline (speedup 1.0000x reference)
#include <cuda_runtime.h>
#include <math.h>

#define N_NODES 50000
#define N_EDGES 800000
#define ND 128
#define ED 64
#define HID 320
#define PCOLS 512

// Scratch (device globals: allocation-guard safe)
__device__ float g_P[(size_t)N_NODES * PCOLS];   // node projections [N, 512]
__device__ float g_Wn[128 * 512];                // packed node weights  [k][j]
__device__ float g_We2[64 * 256];                // packed edge weights  [k][j] (j<128 val, j>=128 mul)

// ---------------------------------------------------------------------------
// Pack weights: Wn[k][j] and We2[k][j] from W_val/W_mul (each [128][320]).
// c = [x_s(0:128), x_r(128:256), ef(256:320)]
// ---------------------------------------------------------------------------
__global__ void pack_weights_kernel(const float* __restrict__ Wv,
                                    const float* __restrict__ Wm) {
    int i = blockIdx.x * blockDim.x + threadIdx.x;
    if (i < 128 * 512) {
        int k = i >> 9, j = i & 511;
        float v;
        if (j < 128)      v = Wv[j * HID + k];              // Ws_val
        else if (j < 256) v = Wv[(j - 128) * HID + 128 + k]; // Wr_val
        else if (j < 384) v = Wm[(j - 256) * HID + k];       // Ws_mul
        else              v = Wm[(j - 384) * HID + 128 + k]; // Wr_mul
        g_Wn[i] = v;
    }
    if (i < 64 * 256) {
        int k = i >> 8, j = i & 255;
        g_We2[i] = (j < 128) ? Wv[j * HID + 256 + k]
                             : Wm[(j - 128) * HID + 256 + k];
    }
}

__global__ void zero_out_kernel(float4* __restrict__ out, int n4) {
    int i = blockIdx.x * blockDim.x + threadIdx.x;
    if (i < n4) out[i] = make_float4(0.f, 0.f, 0.f, 0.f);
}

// ---------------------------------------------------------------------------
// Node GEMM: P[50000,512] = X[50000,128] @ Wn[128,512]
// 128x128 block tile, 8x8 per-thread micro-tile, BK=16.
// ---------------------------------------------------------------------------
__global__ __launch_bounds__(256) void node_gemm_kernel(const float* __restrict__ X) {
    __shared__ float As[16][132];   // [k][m], padded
    __shared__ float Bs[16][128];   // [k][n]
    int m0 = blockIdx.x * 128;
    int n0 = blockIdx.y * 128;
    int tid = threadIdx.x;
    int tm = tid >> 4;   // 0..15
    int tn = tid & 15;   // 0..15

    float acc[8][8];
    #pragma unroll
    for (int i = 0; i < 8; i++)
        #pragma unroll
        for (int j = 0; j < 8; j++) acc[i][j] = 0.f;

    for (int k0 = 0; k0 < 128; k0 += 16) {
        #pragma unroll
        for (int i = 0; i < 8; i++) {
            int lin = tid + i * 256;
            int k = lin & 15, m = lin >> 4;
            int gm = m0 + m;
            As[k][m] = (gm < N_NODES) ? X[(size_t)gm * ND + k0 + k] : 0.f;
        }
        #pragma unroll
        for (int i = 0; i < 8; i++) {
            int lin = tid + i * 256;
            int n = lin & 127, k = lin >> 7;
            Bs[k][n] = g_Wn[(k0 + k) * 512 + n0 + n];
        }
        __syncthreads();
        #pragma unroll
        for (int k = 0; k < 16; k++) {
            float a[8], b[8];
            #pragma unroll
            for (int i = 0; i < 8; i++) a[i] = As[k][tm * 8 + i];
            #pragma unroll
            for (int j = 0; j < 8; j++) b[j] = Bs[k][tn * 8 + j];
            #pragma unroll
            for (int i = 0; i < 8; i++)
                #pragma unroll
                for (int j = 0; j < 8; j++)
                    acc[i][j] = fmaf(a[i], b[j], acc[i][j]);
        }
        __syncthreads();
    }

    #pragma unroll
    for (int i = 0; i < 8; i++) {
        int gm = m0 + tm * 8 + i;
        if (gm < N_NODES) {
            #pragma unroll
            for (int j = 0; j < 8; j += 4) {
                float4 v = make_float4(acc[i][j], acc[i][j+1], acc[i][j+2], acc[i][j+3]);
                *(float4*)&g_P[(size_t)gm * 512 + n0 + tn * 8 + j] = v;
            }
        }
    }
}

// ---------------------------------------------------------------------------
// Fused edge kernel (persistent): per 64-edge tile,
//   Q = ef_tile[64,64] @ We2[64,256]  (register fragments, 8 edges x (4 val + 4 mul) dims)
//   logits = Q + gathered P terms + bias;  msg = softplus(v)*sigmoid(m)
//   atomicAdd into out[receiver].
// Thread (eg = tid/32, dg = tid%32) owns edges eg*8..+7, dims dg*4..+3 (val AND mul).
// Warp (fixed eg) covers all 128 dims -> P gathers + atomics are fully coalesced.
// ---------------------------------------------------------------------------
#define TE 64
#define EDGE_SMEM ((64 * 256 + 64 * 65) * 4 + 64 * 2 * 4)

__device__ __forceinline__ float softplus_f(float x) {
    return fmaxf(x, 0.f) + log1pf(__expf(-fabsf(x)));
}
__device__ __forceinline__ float sigmoid_f(float x) {
    return 1.f / (1.f + __expf(-x));
}

__global__ __launch_bounds__(256, 2) void edge_kernel(
    const float* __restrict__ ef, const int* __restrict__ ei,
    const float* __restrict__ b_val, const float* __restrict__ b_mul,
    float* __restrict__ out)
{
    extern __shared__ float sh[];
    float* W_sh = sh;                    // [64][256]
    float* efT  = sh + 64 * 256;         // [64][65]  efT[k][e] (padded, conflict-free)
    int*  s_sh  = (int*)(efT + 64 * 65); // [64]
    int*  r_sh  = s_sh + 64;             // [64]

    int tid = threadIdx.x;
    int eg = tid >> 5;        // 0..7  (edge group)
    int dg = tid & 31;        // 0..31 (dim group)
    int d0 = dg * 4;

    // Load edge weights once per block
    for (int i = tid; i < 64 * 256; i += 256) W_sh[i] = g_We2[i];

    const float4 bv = *(const float4*)&b_val[d0];
    const float4 bm = *(const float4*)&b_mul[d0];

    __syncthreads();

    const int ntiles = N_EDGES / TE;   // 12500
    for (int tile = blockIdx.x; tile < ntiles; tile += gridDim.x) {
        int e0 = tile * TE;

        if (tid < 64) {
            s_sh[tid] = ei[e0 + tid];
            r_sh[tid] = ei[N_EDGES + e0 + tid];
        }
        for (int i = tid; i < 64 * 64; i += 256) {
            int e = i >> 6, k = i & 63;
            efT[k * 65 + e] = ef[(size_t)(e0 + e) * ED + k];
        }
        __syncthreads();

        float acc[8][8];
        #pragma unroll
        for (int i = 0; i < 8; i++)
            #pragma unroll
            for (int j = 0; j < 8; j++) acc[i][j] = 0.f;

        const float* efb = efT + eg * 8;
        #pragma unroll 4
        for (int k = 0; k < 64; k++) {
            float a[8];
            #pragma unroll
            for (int i = 0; i < 8; i++) a[i] = efb[k * 65 + i];
            float4 blo = *(const float4*)&W_sh[k * 256 + d0];        // val dims
            float4 bhi = *(const float4*)&W_sh[k * 256 + 128 + d0];  // mul dims
            #pragma unroll
            for (int i = 0; i < 8; i++) {
                acc[i][0] = fmaf(a[i], blo.x, acc[i][0]);
                acc[i][1] = fmaf(a[i], blo.y, acc[i][1]);
                acc[i][2] = fmaf(a[i], blo.z, acc[i][2]);
                acc[i][3] = fmaf(a[i], blo.w, acc[i][3]);
                acc[i][4] = fmaf(a[i], bhi.x, acc[i][4]);
                acc[i][5] = fmaf(a[i], bhi.y, acc[i][5]);
                acc[i][6] = fmaf(a[i], bhi.z, acc[i][6]);
                acc[i][7] = fmaf(a[i], bhi.w, acc[i][7]);
            }
        }

        // Epilogue: gather P, activations, scatter
        #pragma unroll
        for (int i = 0; i < 8; i++) {
            int el = eg * 8 + i;
            int s = s_sh[el];
            int r = r_sh[el];
            const float4 psv = *(const float4*)&g_P[(size_t)s * 512 + d0];
            const float4 prv = *(const float4*)&g_P[(size_t)r * 512 + 128 + d0];
            const float4 psm = *(const float4*)&g_P[(size_t)s * 512 + 256 + d0];
            const float4 prm = *(const float4*)&g_P[(size_t)r * 512 + 384 + d0];

            float v0 = acc[i][0] + psv.x + prv.x + bv.x;
            float v1 = acc[i][1] + psv.y + prv.y + bv.y;
            float v2 = acc[i][2] + psv.z + prv.z + bv.z;
            float v3 = acc[i][3] + psv.w + prv.w + bv.w;
            float m0_ = acc[i][4] + psm.x + prm.x + bm.x;
            float m1_ = acc[i][5] + psm.y + prm.y + bm.y;
            float m2_ = acc[i][6] + psm.z + prm.z + bm.z;
            float m3_ = acc[i][7] + psm.w + prm.w + bm.w;

            float g0 = softplus_f(v0) * sigmoid_f(m0_);
            float g1 = softplus_f(v1) * sigmoid_f(m1_);
            float g2 = softplus_f(v2) * sigmoid_f(m2_);
            float g3 = softplus_f(v3) * sigmoid_f(m3_);

            float* op = out + (size_t)r * ND + d0;
            atomicAdd(op + 0, g0);
            atomicAdd(op + 1, g1);
            atomicAdd(op + 2, g2);
            atomicAdd(op + 3, g3);
        }
        __syncthreads();   // protect efT / idx before next tile's loads
    }
}

// ---------------------------------------------------------------------------
extern "C" void kernel_launch(void* const* d_in, const int* in_sizes, int n_in,
                              void* d_out, int out_size) {
    const float* x   = (const float*)d_in[0];
    const int*   ei  = (const int*)  d_in[1];
    const float* ef  = (const float*)d_in[2];
    const float* Wv  = (const float*)d_in[3];
    const float* bv  = (const float*)d_in[4];
    const float* Wm  = (const float*)d_in[5];
    const float* bm  = (const float*)d_in[6];
    float* out = (float*)d_out;

    cudaFuncSetAttribute(edge_kernel,
                         cudaFuncAttributeMaxDynamicSharedMemorySize, EDGE_SMEM);

    pack_weights_kernel<<<(128 * 512 + 255) / 256, 256>>>(Wv, Wm);

    int n4 = N_NODES * ND / 4;
    zero_out_kernel<<<(n4 + 255) / 256, 256>>>((float4*)out, n4);

    node_gemm_kernel<<<dim3((N_NODES + 127) / 128, 4), 256>>>(x);

    edge_kernel<<<296, 256, EDGE_SMEM>>>(ef, ei, bv, bm, out);
}